// round 1
// baseline (speedup 1.0000x reference)
#include <cuda_runtime.h>
#include <math.h>

#define B_ROWS 16384
#define N0     2048
#define NCLS   12
#define NCLU   24
#define NDIM   4
#define NCOL   348       // 12 + 12*24 + 12*4
#define NPAD   384       // padded to 3 * 128

// ---------------- device scratch (allowed: static __device__ globals) --------
__device__ float g_Wt[N0 * NPAD];        // [k][j] row-major, ~3.1 MB
__device__ float g_bias[NPAD];
__device__ float g_Y[(size_t)B_ROWS * NPAD];  // ~25.2 MB

// ---------------- output layout (tuple concatenation) ------------------------
// y0:    [B,12]      at 0
// y1sel: [B,24]      at B*12
// y2sel: [B,4]       at B*36
// Plc:   [B,24,12]   at B*40
#define Y0_OFF   0
#define Y1_OFF   ((size_t)B_ROWS * 12)
#define Y2_OFF   ((size_t)B_ROWS * 36)
#define PLC_OFF  ((size_t)B_ROWS * 40)

// ============================================================================
// Kernel 1: pack weights into a single [N0][NPAD] matrix + bias vector.
// Column mapping j:
//   j in [0,12):    y0 class head, c=j
//   j in [12,300):  y1 bins, t=j-12, c=t/24, k=t%24  -> y1[b,k,c] = Y[b][12+c*24+k]
//   j in [300,348): y2 res,  t=j-300, c=t/4, n=t%4   -> y2[b,n,c] = Y[b][300+c*4+n]
// ============================================================================
__global__ void pack_kernel(const float* __restrict__ Wfc,  const float* __restrict__ bfc,
                            const float* __restrict__ Wbin, const float* __restrict__ bbin,
                            const float* __restrict__ Wres, const float* __restrict__ bres) {
    int idx = blockIdx.x * blockDim.x + threadIdx.x;
    if (idx < N0 * NPAD) {
        int k = idx / NPAD;
        int j = idx - k * NPAD;
        float v = 0.f;
        if (j < 12) {
            v = Wfc[k * NCLS + j];
        } else if (j < 300) {
            int t = j - 12, c = t / NCLU, kk = t - c * NCLU;
            v = Wbin[((size_t)c * N0 + k) * NCLU + kk];
        } else if (j < NCOL) {
            int t = j - 300, c = t / NDIM, n = t - c * NDIM;
            v = Wres[((size_t)c * N0 + k) * NDIM + n];
        }
        g_Wt[idx] = v;
    }
    if (idx < NPAD) {
        float bv = 0.f;
        if (idx < 12) {
            bv = bfc[idx];
        } else if (idx < 300) {
            int t = idx - 12, c = t / NCLU, kk = t - c * NCLU;
            bv = bbin[c * NCLU + kk];
        } else if (idx < NCOL) {
            int t = idx - 300, c = t / NDIM, n = t - c * NDIM;
            bv = bres[c * NDIM + n];
        }
        g_bias[idx] = bv;
    }
}

// ============================================================================
// Kernel 2: fp32 SGEMM  Y[B_ROWS][NPAD] = x[B_ROWS][N0] @ g_Wt[N0][NPAD] + bias
// Classic 128x128x8 block tile, 256 threads, 8x8 per-thread microtile.
// ============================================================================
#define BM 128
#define BN 128
#define BK 8
#define TM 8
#define TN 8

__global__ __launch_bounds__(256) void sgemm_kernel(const float* __restrict__ A) {
    __shared__ float As[BK][BM];   // transposed A tile
    __shared__ float Bs[BK][BN];

    const int bm = blockIdx.y * BM;
    const int bn = blockIdx.x * BN;
    const int t  = threadIdx.x;

    // A tile load: 128 rows x 8 k -> one float4 per thread (over k)
    const int arow = t >> 1;           // 0..127
    const int acol = (t & 1) * 4;      // 0 or 4
    // B tile load: 8 k x 128 n -> one float4 per thread (over n)
    const int brow = t >> 5;           // 0..7
    const int bcol = (t & 31) * 4;     // 0..124

    const int trow = (t >> 4) * TM;    // 0,8,...,120
    const int tcol = (t & 15) * TN;

    float acc[TM][TN];
#pragma unroll
    for (int i = 0; i < TM; i++)
#pragma unroll
        for (int j = 0; j < TN; j++) acc[i][j] = 0.f;

    const float* Aptr = A + (size_t)(bm + arow) * N0 + acol;
    const float* Bptr = g_Wt + (size_t)brow * NPAD + bn + bcol;

    for (int k0 = 0; k0 < N0; k0 += BK) {
        float4 av = *(const float4*)(Aptr + k0);
        As[acol + 0][arow] = av.x;
        As[acol + 1][arow] = av.y;
        As[acol + 2][arow] = av.z;
        As[acol + 3][arow] = av.w;
        *(float4*)&Bs[brow][bcol] = *(const float4*)(Bptr + (size_t)k0 * NPAD);
        __syncthreads();

#pragma unroll
        for (int kk = 0; kk < BK; kk++) {
            float ra[TM], rb[TN];
            *(float4*)&ra[0] = *(const float4*)&As[kk][trow];
            *(float4*)&ra[4] = *(const float4*)&As[kk][trow + 4];
            *(float4*)&rb[0] = *(const float4*)&Bs[kk][tcol];
            *(float4*)&rb[4] = *(const float4*)&Bs[kk][tcol + 4];
#pragma unroll
            for (int i = 0; i < TM; i++)
#pragma unroll
                for (int j = 0; j < TN; j++)
                    acc[i][j] = fmaf(ra[i], rb[j], acc[i][j]);
        }
        __syncthreads();
    }

#pragma unroll
    for (int i = 0; i < TM; i++) {
        float* cp = g_Y + (size_t)(bm + trow + i) * NPAD + bn + tcol;
#pragma unroll
        for (int j = 0; j < TN; j++)
            cp[j] = acc[i][j] + g_bias[bn + tcol + j];
    }
}

// ============================================================================
// Kernel 3: epilogue. One warp per row (8 rows per 256-thread block).
//  - Pc = softmax(y0) over 12 classes
//  - per-class softmax over 24 clusters; Plc = Pl * Pc
//  - flat argmax over [k][c] (flat idx = k*12 + c, first-index tie-break)
//  - gathers + writes
// ============================================================================
__global__ __launch_bounds__(256) void epilogue_kernel(float* __restrict__ out) {
    const int warp = threadIdx.x >> 5;
    const int lane = threadIdx.x & 31;
    const int row  = blockIdx.x * 8 + warp;

    __shared__ float sY[8][NCOL];

    const float* yr = g_Y + (size_t)row * NPAD;
    for (int j = lane; j < NCOL; j += 32) sY[warp][j] = yr[j];
    __syncwarp();

    const float* s = sY[warp];

    // ---- Pc = softmax over lanes 0..11 of y0 ----
    float y0v = (lane < NCLS) ? s[lane] : -INFINITY;
    float m = y0v;
#pragma unroll
    for (int o = 16; o; o >>= 1) m = fmaxf(m, __shfl_xor_sync(0xFFFFFFFFu, m, o));
    float e = (lane < NCLS) ? expf(y0v - m) : 0.f;
    float ssum = e;
#pragma unroll
    for (int o = 16; o; o >>= 1) ssum += __shfl_xor_sync(0xFFFFFFFFu, ssum, o);
    float Pc = e / ssum;

    // ---- per-class cluster softmax, Plc writes, per-lane argmax ----
    float best = -1.f;
    int bestk = 0;
    if (lane < NCLS) {
        const float* yc = s + 12 + lane * NCLU;
        float mc = -INFINITY;
#pragma unroll
        for (int k = 0; k < NCLU; k++) mc = fmaxf(mc, yc[k]);
        float sc = 0.f;
#pragma unroll
        for (int k = 0; k < NCLU; k++) sc += expf(yc[k] - mc);
        float inv = Pc / sc;
        float* pout = out + PLC_OFF + (size_t)row * (NCLU * NCLS) + lane;
#pragma unroll
        for (int k = 0; k < NCLU; k++) {
            float p = expf(yc[k] - mc) * inv;
            pout[k * NCLS] = p;
            if (p > best) { best = p; bestk = k; }
        }
    }

    // ---- flat argmax across lanes (value desc, flat index asc on ties) ----
    float bv = best;
    int bi = bestk * NCLS + lane;   // flat index k*12 + c
#pragma unroll
    for (int o = 16; o; o >>= 1) {
        float ov = __shfl_xor_sync(0xFFFFFFFFu, bv, o);
        int   oi = __shfl_xor_sync(0xFFFFFFFFu, bi, o);
        if (ov > bv || (ov == bv && oi < bi)) { bv = ov; bi = oi; }
    }
    const int ic = bi % NCLS;

    // ---- outputs ----
    if (lane < NCLS) out[Y0_OFF + (size_t)row * NCLS + lane] = s[lane];
    if (lane < NCLU) out[Y1_OFF + (size_t)row * NCLU + lane] = s[12 + ic * NCLU + lane];
    if (lane < NDIM) out[Y2_OFF + (size_t)row * NDIM + lane] = s[300 + ic * NDIM + lane];
}

// ============================================================================
extern "C" void kernel_launch(void* const* d_in, const int* in_sizes, int n_in,
                              void* d_out, int out_size) {
    const float* x    = (const float*)d_in[0];
    const float* Wfc  = (const float*)d_in[1];
    const float* bfc  = (const float*)d_in[2];
    const float* Wbin = (const float*)d_in[3];
    const float* bbin = (const float*)d_in[4];
    const float* Wres = (const float*)d_in[5];
    const float* bres = (const float*)d_in[6];
    float* out = (float*)d_out;

    pack_kernel<<<(N0 * NPAD + 255) / 256, 256>>>(Wfc, bfc, Wbin, bbin, Wres, bres);

    dim3 grid(NPAD / BN, B_ROWS / BM);
    sgemm_kernel<<<grid, 256>>>(x);

    epilogue_kernel<<<B_ROWS / 8, 256>>>(out);
}

// round 6
// speedup vs baseline: 1.8624x; 1.8624x over previous
#include <cuda_runtime.h>
#include <cuda_bf16.h>
#include <math.h>
#include <stdint.h>

#define B_ROWS 16384
#define N0     2048
#define NCLS   12
#define NCLU   24
#define NDIM   4
#define NCOL   348
#define NPAD   384

// GEMM tiling
#define BM 128
#define BN 96
#define BK 32
#define THREADS 256
#define KCHUNKS (N0 / BK)     // 64

// smem stage layout (bytes); rows padded to 40 bf16 (80B) => conflict-free ldmatrix
#define ST_AH 0
#define ST_AL 10240           // 128*80
#define ST_BH 20480
#define ST_BL 28160           // + 96*80
#define STAGE 35840
#define SMEM_TOTAL (2 * STAGE)  // 71680

// ----------------------------- device scratch ------------------------------
__device__ float g_Wt[N0 * NPAD];                  // fp32 packed weights (fixup)
__device__ float g_bias[NPAD];
__device__ float g_Y[(size_t)B_ROWS * NPAD];       // GEMM output
__device__ __align__(16) __nv_bfloat16 g_Bh[NPAD * N0];  // W^T hi, [n][k]
__device__ __align__(16) __nv_bfloat16 g_Bl[NPAD * N0];  // W^T lo, [n][k]
__device__ int g_flagcnt;
__device__ int g_flagrows[B_ROWS];

// output layout (tuple concat) — validated in round 1
#define Y0_OFF   0
#define Y1_OFF   ((size_t)B_ROWS * 12)
#define Y2_OFF   ((size_t)B_ROWS * 36)
#define PLC_OFF  ((size_t)B_ROWS * 40)

// ----------------------------- PTX helpers ---------------------------------
__device__ __forceinline__ uint32_t smem_u32(const void* p) {
    uint32_t a;
    asm("{ .reg .u64 t; cvta.to.shared.u64 t, %1; cvt.u32.u64 %0, t; }" : "=r"(a) : "l"(p));
    return a;
}
#define CP_ASYNC16(dst, src) \
    asm volatile("cp.async.cg.shared.global [%0], [%1], 16;" :: "r"(dst), "l"(src))
#define CP_COMMIT() asm volatile("cp.async.commit_group;" ::: "memory")
#define CP_WAIT0()  asm volatile("cp.async.wait_group 0;" ::: "memory")

#define LDMATRIX_X4(r0, r1, r2, r3, addr) \
    asm volatile("ldmatrix.sync.aligned.m8n8.x4.shared.b16 {%0,%1,%2,%3}, [%4];" \
                 : "=r"(r0), "=r"(r1), "=r"(r2), "=r"(r3) : "r"(addr))

#define MMA_BF16(d, a, b0, b1) \
    asm volatile("mma.sync.aligned.m16n8k16.row.col.f32.bf16.bf16.f32 " \
                 "{%0,%1,%2,%3}, {%4,%5,%6,%7}, {%8,%9}, {%0,%1,%2,%3};" \
                 : "+f"((d)[0]), "+f"((d)[1]), "+f"((d)[2]), "+f"((d)[3]) \
                 : "r"((a)[0]), "r"((a)[1]), "r"((a)[2]), "r"((a)[3]), "r"(b0), "r"(b1))

// ----------------------------- packing -------------------------------------
__device__ __forceinline__ float colval(int j, int k, const float* Wfc,
                                        const float* Wbin, const float* Wres) {
    if (j < 12) return Wfc[k * NCLS + j];
    if (j < 300) { int t = j - 12, c = t / NCLU, kk = t - c * NCLU;
                   return Wbin[((size_t)c * N0 + k) * NCLU + kk]; }
    if (j < NCOL) { int t = j - 300, c = t / NDIM, n = t - c * NDIM;
                    return Wres[((size_t)c * N0 + k) * NDIM + n]; }
    return 0.f;
}

__global__ void pack_kernel(const float* __restrict__ Wfc,  const float* __restrict__ bfc,
                            const float* __restrict__ Wbin, const float* __restrict__ bbin,
                            const float* __restrict__ Wres, const float* __restrict__ bres) {
    int idx = blockIdx.x * blockDim.x + threadIdx.x;
    if (idx == 0) g_flagcnt = 0;
    if (idx < N0 * NPAD) {            // g_Wt [k][j], coalesced in j
        int k = idx / NPAD, j = idx - k * NPAD;
        g_Wt[idx] = colval(j, k, Wfc, Wbin, Wres);
    }
    if (idx < NPAD) {
        float bv = 0.f;
        if (idx < 12) bv = bfc[idx];
        else if (idx < 300) { int t = idx - 12, c = t / NCLU, kk = t - c * NCLU; bv = bbin[c * NCLU + kk]; }
        else if (idx < NCOL) { int t = idx - 300, c = t / NDIM, n = t - c * NDIM; bv = bres[c * NDIM + n]; }
        g_bias[idx] = bv;
    }
    // region 2: bf16 hi/lo transposed weights [n][k], 8 k per thread
    int t = idx - N0 * NPAD;
    if (t >= 0 && t < NPAD * (N0 / 8)) {
        int n = t / (N0 / 8);
        int k0 = (t % (N0 / 8)) * 8;
        float v[8];
#pragma unroll
        for (int e = 0; e < 8; e++) v[e] = colval(n, k0 + e, Wfc, Wbin, Wres);
        uint32_t hp[4], lp[4];
#pragma unroll
        for (int i = 0; i < 4; i++) {
            __nv_bfloat162 h2 = __floats2bfloat162_rn(v[2*i], v[2*i+1]);
            float r0 = v[2*i]   - __bfloat162float(h2.x);
            float r1 = v[2*i+1] - __bfloat162float(h2.y);
            __nv_bfloat162 l2 = __floats2bfloat162_rn(r0, r1);
            hp[i] = *reinterpret_cast<uint32_t*>(&h2);
            lp[i] = *reinterpret_cast<uint32_t*>(&l2);
        }
        *reinterpret_cast<uint4*>(&g_Bh[n * N0 + k0]) = make_uint4(hp[0], hp[1], hp[2], hp[3]);
        *reinterpret_cast<uint4*>(&g_Bl[n * N0 + k0]) = make_uint4(lp[0], lp[1], lp[2], lp[3]);
    }
}

// ----------------------------- mma.sync GEMM -------------------------------
// Y[16384][384] = x @ W (+bias later), 3-term bf16 split, fp32 accum.
// grid = (4, 128): blockIdx.x = n-tile (L2 reuse of x across the 4), .y = m-tile
__global__ __launch_bounds__(THREADS) void gemm_kernel(const float* __restrict__ x) {
    extern __shared__ char smem[];
    const uint32_t sb = smem_u32(smem);
    const int tid  = threadIdx.x;
    const int lane = tid & 31;
    const int wid  = tid >> 5;
    const int wm   = wid >> 1;          // 0..3
    const int wn   = wid & 1;           // 0..1
    const int bm   = blockIdx.y * BM;
    const int bn   = blockIdx.x * BN;

    float acc[2][6][4];
#pragma unroll
    for (int i = 0; i < 2; i++)
#pragma unroll
        for (int j = 0; j < 6; j++)
#pragma unroll
            for (int q = 0; q < 4; q++) acc[i][j][q] = 0.f;

    // ---- B cp.async loader: 96 rows x 32 k, hi+lo = 768 x 16B over 256 thr --
    auto loadB = [&](int c, int s) {
#pragma unroll
        for (int it = 0; it < 3; ++it) {
            int g = tid + it * 256;                 // 0..767
            int half = (g >= 384);
            int idx2 = g - half * 384;
            int row = idx2 >> 2, seg = idx2 & 3;
            const __nv_bfloat16* src = (half ? g_Bl : g_Bh)
                                     + (size_t)(bn + row) * N0 + c * BK + seg * 8;
            uint32_t dst = sb + s * STAGE + (half ? ST_BL : ST_BH) + row * 80 + seg * 16;
            CP_ASYNC16(dst, src);
        }
        CP_COMMIT();
    };
    // ---- A loads: 128 rows x 32 k fp32 = 1024 float4 over 256 thr ----------
    float4 areg[4];
    auto loadA = [&](int c) {
#pragma unroll
        for (int it = 0; it < 4; ++it) {
            int idx2 = tid + it * 256;              // 0..1023
            int row = idx2 >> 3, seg = idx2 & 7;
            areg[it] = *reinterpret_cast<const float4*>(
                x + (size_t)(bm + row) * N0 + c * BK + seg * 4);
        }
    };
    auto storeA = [&](int s) {
#pragma unroll
        for (int it = 0; it < 4; ++it) {
            int idx2 = tid + it * 256;
            int row = idx2 >> 3, seg = idx2 & 7;
            float v[4] = {areg[it].x, areg[it].y, areg[it].z, areg[it].w};
            uint32_t hp[2], lp[2];
#pragma unroll
            for (int i = 0; i < 2; i++) {
                __nv_bfloat162 h2 = __floats2bfloat162_rn(v[2*i], v[2*i+1]);
                float r0 = v[2*i]   - __bfloat162float(h2.x);
                float r1 = v[2*i+1] - __bfloat162float(h2.y);
                __nv_bfloat162 l2 = __floats2bfloat162_rn(r0, r1);
                hp[i] = *reinterpret_cast<uint32_t*>(&h2);
                lp[i] = *reinterpret_cast<uint32_t*>(&l2);
            }
            char* base = smem + s * STAGE;
            *reinterpret_cast<uint2*>(base + ST_AH + row * 80 + seg * 8) = make_uint2(hp[0], hp[1]);
            *reinterpret_cast<uint2*>(base + ST_AL + row * 80 + seg * 8) = make_uint2(lp[0], lp[1]);
        }
    };

    // ---- compute one BK=32 chunk from stage s ------------------------------
    auto compute = [&](int s) {
        const uint32_t st = sb + s * STAGE;
        // ldmatrix address components
        const int arow = wm * 32 + (lane & 15);
        const int acol8 = (lane >> 4) * 8;
        const int brow = wn * 48 + ((lane >> 4) & 1) * 8 + (lane & 7);
        const int bcol8 = ((lane >> 3) & 1) * 8;
#pragma unroll
        for (int kk = 0; kk < BK; kk += 16) {
            uint32_t ah[2][4], al[2][4], b[3][4];
#pragma unroll
            for (int mf = 0; mf < 2; mf++) {
                uint32_t ad = st + ST_AH + (arow + mf * 16) * 80 + (kk + acol8) * 2;
                LDMATRIX_X4(ah[mf][0], ah[mf][1], ah[mf][2], ah[mf][3], ad);
                uint32_t adl = st + ST_AL + (arow + mf * 16) * 80 + (kk + acol8) * 2;
                LDMATRIX_X4(al[mf][0], al[mf][1], al[mf][2], al[mf][3], adl);
            }
#pragma unroll
            for (int bq = 0; bq < 3; bq++) {
                uint32_t bd = st + ST_BH + (brow + bq * 16) * 80 + (kk + bcol8) * 2;
                LDMATRIX_X4(b[bq][0], b[bq][1], b[bq][2], b[bq][3], bd);
            }
            // term 1 + 2: (Ah + Al) x Bh
#pragma unroll
            for (int mf = 0; mf < 2; mf++)
#pragma unroll
                for (int nf = 0; nf < 6; nf++) {
                    int bq = nf >> 1, o = (nf & 1) * 2;
                    MMA_BF16(acc[mf][nf], ah[mf], b[bq][o], b[bq][o + 1]);
                    MMA_BF16(acc[mf][nf], al[mf], b[bq][o], b[bq][o + 1]);
                }
            // term 3: Ah x Bl
#pragma unroll
            for (int bq = 0; bq < 3; bq++) {
                uint32_t bd = st + ST_BL + (brow + bq * 16) * 80 + (kk + bcol8) * 2;
                LDMATRIX_X4(b[bq][0], b[bq][1], b[bq][2], b[bq][3], bd);
            }
#pragma unroll
            for (int mf = 0; mf < 2; mf++)
#pragma unroll
                for (int nf = 0; nf < 6; nf++) {
                    int bq = nf >> 1, o = (nf & 1) * 2;
                    MMA_BF16(acc[mf][nf], ah[mf], b[bq][o], b[bq][o + 1]);
                }
        }
    };

    // ---- pipeline -----------------------------------------------------------
    loadB(0, 0);
    loadA(0);
    storeA(0);
    CP_WAIT0();
    __syncthreads();
    for (int c = 0; c < KCHUNKS; ++c) {
        int s = c & 1;
        if (c < KCHUNKS - 1) { loadB(c + 1, s ^ 1); loadA(c + 1); }
        compute(s);
        if (c < KCHUNKS - 1) {
            storeA(s ^ 1);
            CP_WAIT0();
            __syncthreads();
        }
    }

    // ---- write out (+bias) --------------------------------------------------
#pragma unroll
    for (int mf = 0; mf < 2; mf++) {
        int r0 = bm + wm * 32 + mf * 16 + (lane >> 2);
#pragma unroll
        for (int nf = 0; nf < 6; nf++) {
            int col = bn + wn * 48 + nf * 8 + (lane & 3) * 2;
            float2 v0 = make_float2(acc[mf][nf][0] + g_bias[col],
                                    acc[mf][nf][1] + g_bias[col + 1]);
            float2 v1 = make_float2(acc[mf][nf][2] + g_bias[col],
                                    acc[mf][nf][3] + g_bias[col + 1]);
            *reinterpret_cast<float2*>(g_Y + (size_t)r0 * NPAD + col) = v0;
            *reinterpret_cast<float2*>(g_Y + (size_t)(r0 + 8) * NPAD + col) = v1;
        }
    }
}

// ----------------------------- epilogue ------------------------------------
__global__ __launch_bounds__(256) void epilogue_kernel(float* __restrict__ out) {
    const int warp = threadIdx.x >> 5;
    const int lane = threadIdx.x & 31;
    const int row  = blockIdx.x * 8 + warp;

    __shared__ float sY[8][NCOL];
    const float* yr = g_Y + (size_t)row * NPAD;
    for (int j = lane; j < NCOL; j += 32) sY[warp][j] = yr[j];
    __syncwarp();
    const float* s = sY[warp];

    float y0v = (lane < NCLS) ? s[lane] : -INFINITY;
    float m = y0v;
#pragma unroll
    for (int o = 16; o; o >>= 1) m = fmaxf(m, __shfl_xor_sync(0xFFFFFFFFu, m, o));
    float e = (lane < NCLS) ? expf(y0v - m) : 0.f;
    float ssum = e;
#pragma unroll
    for (int o = 16; o; o >>= 1) ssum += __shfl_xor_sync(0xFFFFFFFFu, ssum, o);
    float Pc = e / ssum;

    float best = -1.f, sec = -1.f;
    int bestk = 0;
    if (lane < NCLS) {
        const float* yc = s + 12 + lane * NCLU;
        float mc = -INFINITY;
#pragma unroll
        for (int k = 0; k < NCLU; k++) mc = fmaxf(mc, yc[k]);
        float sc = 0.f;
#pragma unroll
        for (int k = 0; k < NCLU; k++) sc += expf(yc[k] - mc);
        float inv = Pc / sc;
        float* pout = out + PLC_OFF + (size_t)row * (NCLU * NCLS) + lane;
#pragma unroll
        for (int k = 0; k < NCLU; k++) {
            float p = expf(yc[k] - mc) * inv;
            pout[k * NCLS] = p;
            if (p > best) { sec = best; best = p; bestk = k; }
            else if (p > sec) sec = p;
        }
    }

    // argmax with first-flat-index tie-break
    float bv = best;
    int bi = bestk * NCLS + lane;
#pragma unroll
    for (int o = 16; o; o >>= 1) {
        float ov = __shfl_xor_sync(0xFFFFFFFFu, bv, o);
        int   oi = __shfl_xor_sync(0xFFFFFFFFu, bi, o);
        if (ov > bv || (ov == bv && oi < bi)) { bv = ov; bi = oi; }
    }
    const int ic = bi % NCLS;

    // top-2 across warp for uncertainty flag
    float t1 = best, t2 = sec;
#pragma unroll
    for (int o = 16; o; o >>= 1) {
        float o1 = __shfl_xor_sync(0xFFFFFFFFu, t1, o);
        float o2 = __shfl_xor_sync(0xFFFFFFFFu, t2, o);
        if (o1 > t1) { t2 = fmaxf(t1, o2); t1 = o1; }
        else         { t2 = fmaxf(t2, o1); }
    }
    if (lane == 0 && (t1 - t2) < 1e-3f * t1) {
        int p = atomicAdd(&g_flagcnt, 1);
        g_flagrows[p] = row;
    }

    if (lane < NCLS) out[Y0_OFF + (size_t)row * NCLS + lane] = s[lane];
    if (lane < NCLU) out[Y1_OFF + (size_t)row * NCLU + lane] = s[12 + ic * NCLU + lane];
    if (lane < NDIM) out[Y2_OFF + (size_t)row * NDIM + lane] = s[300 + ic * NDIM + lane];
}

// ----------------------------- fp32 exact fixup ----------------------------
__global__ __launch_bounds__(512) void fixup_kernel(const float* __restrict__ x,
                                                    float* __restrict__ out) {
    __shared__ float sx[N0];
    __shared__ float sy[NCOL];
    __shared__ float sPc[NCLS];
    __shared__ float sBP[NCLS];
    __shared__ int   sBK[NCLS];
    const int tid = threadIdx.x;
    const int cnt = g_flagcnt;

    for (int f = blockIdx.x; f < cnt; f += gridDim.x) {
        const int row = g_flagrows[f];
        for (int i = tid; i < N0; i += 512) sx[i] = x[(size_t)row * N0 + i];
        __syncthreads();
        if (tid < NCOL) {
            float acc = g_bias[tid];
            const float* w = g_Wt + tid;
#pragma unroll 8
            for (int k = 0; k < N0; k++) acc += sx[k] * w[(size_t)k * NPAD];
            sy[tid] = acc;
        }
        __syncthreads();
        if (tid == 0) {
            float mm = -INFINITY;
            for (int c = 0; c < NCLS; c++) mm = fmaxf(mm, sy[c]);
            float ss = 0.f;
            for (int c = 0; c < NCLS; c++) ss += expf(sy[c] - mm);
            for (int c = 0; c < NCLS; c++) sPc[c] = expf(sy[c] - mm) / ss;
        }
        __syncthreads();
        if (tid < NCLS) {
            const float* yc = sy + 12 + tid * NCLU;
            float mc = -INFINITY;
            for (int k = 0; k < NCLU; k++) mc = fmaxf(mc, yc[k]);
            float sc = 0.f;
            for (int k = 0; k < NCLU; k++) sc += expf(yc[k] - mc);
            float inv = sPc[tid] / sc;
            float b = -1.f; int bk = 0;
            for (int k = 0; k < NCLU; k++) {
                float p = expf(yc[k] - mc) * inv;
                if (p > b) { b = p; bk = k; }
            }
            sBP[tid] = b; sBK[tid] = bk;
        }
        __syncthreads();
        if (tid == 0) {
            float bp = -1.f; int bi = 0x7FFFFFFF;
            for (int c = 0; c < NCLS; c++) {
                int flat = sBK[c] * NCLS + c;
                if (sBP[c] > bp || (sBP[c] == bp && flat < bi)) { bp = sBP[c]; bi = flat; }
            }
            int ic = bi % NCLS;
            for (int k = 0; k < NCLU; k++)
                out[Y1_OFF + (size_t)row * NCLU + k] = sy[12 + ic * NCLU + k];
            for (int n = 0; n < NDIM; n++)
                out[Y2_OFF + (size_t)row * NDIM + n] = sy[300 + ic * NDIM + n];
        }
        __syncthreads();
    }
}

// ============================================================================
extern "C" void kernel_launch(void* const* d_in, const int* in_sizes, int n_in,
                              void* d_out, int out_size) {
    const float* x    = (const float*)d_in[0];
    const float* Wfc  = (const float*)d_in[1];
    const float* bfc  = (const float*)d_in[2];
    const float* Wbin = (const float*)d_in[3];
    const float* bbin = (const float*)d_in[4];
    const float* Wres = (const float*)d_in[5];
    const float* bres = (const float*)d_in[6];
    float* out = (float*)d_out;

    static bool attr_set = false;
    if (!attr_set) {
        cudaFuncSetAttribute(gemm_kernel, cudaFuncAttributeMaxDynamicSharedMemorySize, SMEM_TOTAL);
        attr_set = true;
    }

    int pack_tasks = N0 * NPAD + NPAD * (N0 / 8);
    pack_kernel<<<(pack_tasks + 255) / 256, 256>>>(Wfc, bfc, Wbin, bbin, Wres, bres);

    gemm_kernel<<<dim3(NPAD / BN, B_ROWS / BM), THREADS, SMEM_TOTAL>>>(x);

    epilogue_kernel<<<B_ROWS / 8, 256>>>(out);

    fixup_kernel<<<96, 512>>>(x, out);
}

// round 8
// speedup vs baseline: 2.2861x; 1.2275x over previous
#include <cuda_runtime.h>
#include <cuda_bf16.h>
#include <math.h>
#include <stdint.h>

#define B_ROWS 16384
#define N0     2048
#define NCLS   12
#define NCLU   24
#define NDIM   4
#define NCOL   348
#define NPAD   384

// GEMM tiling
#define BM 128
#define BN 96
#define BK 32
#define THREADS 256
#define KCHUNKS (N0 / BK)     // 64

// smem stage layout (bytes); rows padded to 40 bf16 (80B) => conflict-free ldmatrix
#define ST_AH 0
#define ST_AL 10240           // 128*80
#define ST_BH 20480
#define ST_BL 28160           // + 96*80
#define STAGE 35840
#define SMEM_TOTAL (2 * STAGE)  // 71680

// ----------------------------- device scratch ------------------------------
__device__ float g_Wt[N0 * NPAD];                  // fp32 packed weights (fixup)
__device__ float g_bias[NPAD];
__device__ float g_Y[(size_t)B_ROWS * NPAD];       // GEMM output
__device__ __align__(16) __nv_bfloat16 g_Bh[NPAD * N0];  // W^T hi, [n][k]
__device__ __align__(16) __nv_bfloat16 g_Bl[NPAD * N0];  // W^T lo, [n][k]
__device__ int g_flagcnt;
__device__ int g_flagrows[B_ROWS];

// output layout (tuple concat) — validated in round 1
#define Y0_OFF   0
#define Y1_OFF   ((size_t)B_ROWS * 12)
#define Y2_OFF   ((size_t)B_ROWS * 36)
#define PLC_OFF  ((size_t)B_ROWS * 40)

// ----------------------------- PTX helpers ---------------------------------
__device__ __forceinline__ uint32_t smem_u32(const void* p) {
    uint32_t a;
    asm("{ .reg .u64 t; cvta.to.shared.u64 t, %1; cvt.u32.u64 %0, t; }" : "=r"(a) : "l"(p));
    return a;
}
#define CP_ASYNC16(dst, src) \
    asm volatile("cp.async.cg.shared.global [%0], [%1], 16;" :: "r"(dst), "l"(src))
#define CP_COMMIT() asm volatile("cp.async.commit_group;" ::: "memory")
#define CP_WAIT0()  asm volatile("cp.async.wait_group 0;" ::: "memory")

#define LDMATRIX_X4(r0, r1, r2, r3, addr) \
    asm volatile("ldmatrix.sync.aligned.m8n8.x4.shared.b16 {%0,%1,%2,%3}, [%4];" \
                 : "=r"(r0), "=r"(r1), "=r"(r2), "=r"(r3) : "r"(addr))

#define MMA_BF16(d, a, b0, b1) \
    asm volatile("mma.sync.aligned.m16n8k16.row.col.f32.bf16.bf16.f32 " \
                 "{%0,%1,%2,%3}, {%4,%5,%6,%7}, {%8,%9}, {%0,%1,%2,%3};" \
                 : "+f"((d)[0]), "+f"((d)[1]), "+f"((d)[2]), "+f"((d)[3]) \
                 : "r"((a)[0]), "r"((a)[1]), "r"((a)[2]), "r"((a)[3]), "r"(b0), "r"(b1))

// ----------------------------- packing -------------------------------------
__device__ __forceinline__ float colval(int j, int k, const float* Wfc,
                                        const float* Wbin, const float* Wres) {
    if (j < 12) return Wfc[k * NCLS + j];
    if (j < 300) { int t = j - 12, c = t / NCLU, kk = t - c * NCLU;
                   return Wbin[((size_t)c * N0 + k) * NCLU + kk]; }
    if (j < NCOL) { int t = j - 300, c = t / NDIM, n = t - c * NDIM;
                    return Wres[((size_t)c * N0 + k) * NDIM + n]; }
    return 0.f;
}

__global__ void pack_kernel(const float* __restrict__ Wfc,  const float* __restrict__ bfc,
                            const float* __restrict__ Wbin, const float* __restrict__ bbin,
                            const float* __restrict__ Wres, const float* __restrict__ bres) {
    int idx = blockIdx.x * blockDim.x + threadIdx.x;
    if (idx == 0) g_flagcnt = 0;
    if (idx < N0 * NPAD) {            // g_Wt [k][j], coalesced in j
        int k = idx / NPAD, j = idx - k * NPAD;
        g_Wt[idx] = colval(j, k, Wfc, Wbin, Wres);
    }
    if (idx < NPAD) {
        float bv = 0.f;
        if (idx < 12) bv = bfc[idx];
        else if (idx < 300) { int t = idx - 12, c = t / NCLU, kk = t - c * NCLU; bv = bbin[c * NCLU + kk]; }
        else if (idx < NCOL) { int t = idx - 300, c = t / NDIM, n = t - c * NDIM; bv = bres[c * NDIM + n]; }
        g_bias[idx] = bv;
    }
    // region 2: bf16 hi/lo transposed weights [n][k], 8 k per thread
    int t = idx - N0 * NPAD;
    if (t >= 0 && t < NPAD * (N0 / 8)) {
        int n = t / (N0 / 8);
        int k0 = (t % (N0 / 8)) * 8;
        float v[8];
#pragma unroll
        for (int e = 0; e < 8; e++) v[e] = colval(n, k0 + e, Wfc, Wbin, Wres);
        uint32_t hp[4], lp[4];
#pragma unroll
        for (int i = 0; i < 4; i++) {
            __nv_bfloat162 h2 = __floats2bfloat162_rn(v[2*i], v[2*i+1]);
            float r0 = v[2*i]   - __bfloat162float(h2.x);
            float r1 = v[2*i+1] - __bfloat162float(h2.y);
            __nv_bfloat162 l2 = __floats2bfloat162_rn(r0, r1);
            hp[i] = *reinterpret_cast<uint32_t*>(&h2);
            lp[i] = *reinterpret_cast<uint32_t*>(&l2);
        }
        *reinterpret_cast<uint4*>(&g_Bh[n * N0 + k0]) = make_uint4(hp[0], hp[1], hp[2], hp[3]);
        *reinterpret_cast<uint4*>(&g_Bl[n * N0 + k0]) = make_uint4(lp[0], lp[1], lp[2], lp[3]);
    }
}

// ----------------------------- mma.sync GEMM -------------------------------
// Y[16384][384] = x @ W (+bias), 3-term bf16 split, fp32 accum.
__global__ __launch_bounds__(THREADS) void gemm_kernel(const float* __restrict__ x) {
    extern __shared__ char smem[];
    const uint32_t sb = smem_u32(smem);
    const int tid  = threadIdx.x;
    const int lane = tid & 31;
    const int wid  = tid >> 5;
    const int wm   = wid >> 1;          // 0..3
    const int wn   = wid & 1;           // 0..1
    const int bm   = blockIdx.y * BM;
    const int bn   = blockIdx.x * BN;

    float acc[2][6][4];
#pragma unroll
    for (int i = 0; i < 2; i++)
#pragma unroll
        for (int j = 0; j < 6; j++)
#pragma unroll
            for (int q = 0; q < 4; q++) acc[i][j][q] = 0.f;

    auto loadB = [&](int c, int s) {
#pragma unroll
        for (int it = 0; it < 3; ++it) {
            int g = tid + it * 256;                 // 0..767
            int half = (g >= 384);
            int idx2 = g - half * 384;
            int row = idx2 >> 2, seg = idx2 & 3;
            const __nv_bfloat16* src = (half ? g_Bl : g_Bh)
                                     + (size_t)(bn + row) * N0 + c * BK + seg * 8;
            uint32_t dst = sb + s * STAGE + (half ? ST_BL : ST_BH) + row * 80 + seg * 16;
            CP_ASYNC16(dst, src);
        }
        CP_COMMIT();
    };
    float4 areg[4];
    auto loadA = [&](int c) {
#pragma unroll
        for (int it = 0; it < 4; ++it) {
            int idx2 = tid + it * 256;              // 0..1023
            int row = idx2 >> 3, seg = idx2 & 7;
            areg[it] = *reinterpret_cast<const float4*>(
                x + (size_t)(bm + row) * N0 + c * BK + seg * 4);
        }
    };
    auto storeA = [&](int s) {
#pragma unroll
        for (int it = 0; it < 4; ++it) {
            int idx2 = tid + it * 256;
            int row = idx2 >> 3, seg = idx2 & 7;
            float v[4] = {areg[it].x, areg[it].y, areg[it].z, areg[it].w};
            uint32_t hp[2], lp[2];
#pragma unroll
            for (int i = 0; i < 2; i++) {
                __nv_bfloat162 h2 = __floats2bfloat162_rn(v[2*i], v[2*i+1]);
                float r0 = v[2*i]   - __bfloat162float(h2.x);
                float r1 = v[2*i+1] - __bfloat162float(h2.y);
                __nv_bfloat162 l2 = __floats2bfloat162_rn(r0, r1);
                hp[i] = *reinterpret_cast<uint32_t*>(&h2);
                lp[i] = *reinterpret_cast<uint32_t*>(&l2);
            }
            char* base = smem + s * STAGE;
            *reinterpret_cast<uint2*>(base + ST_AH + row * 80 + seg * 8) = make_uint2(hp[0], hp[1]);
            *reinterpret_cast<uint2*>(base + ST_AL + row * 80 + seg * 8) = make_uint2(lp[0], lp[1]);
        }
    };

    auto compute = [&](int s) {
        const uint32_t st = sb + s * STAGE;
        const int arow = wm * 32 + (lane & 15);
        const int acol8 = (lane >> 4) * 8;
        const int brow = wn * 48 + ((lane >> 4) & 1) * 8 + (lane & 7);
        const int bcol8 = ((lane >> 3) & 1) * 8;
#pragma unroll
        for (int kk = 0; kk < BK; kk += 16) {
            uint32_t ah[2][4], al[2][4], b[3][4];
#pragma unroll
            for (int mf = 0; mf < 2; mf++) {
                uint32_t ad = st + ST_AH + (arow + mf * 16) * 80 + (kk + acol8) * 2;
                LDMATRIX_X4(ah[mf][0], ah[mf][1], ah[mf][2], ah[mf][3], ad);
                uint32_t adl = st + ST_AL + (arow + mf * 16) * 80 + (kk + acol8) * 2;
                LDMATRIX_X4(al[mf][0], al[mf][1], al[mf][2], al[mf][3], adl);
            }
#pragma unroll
            for (int bq = 0; bq < 3; bq++) {
                uint32_t bd = st + ST_BH + (brow + bq * 16) * 80 + (kk + bcol8) * 2;
                LDMATRIX_X4(b[bq][0], b[bq][1], b[bq][2], b[bq][3], bd);
            }
#pragma unroll
            for (int mf = 0; mf < 2; mf++)
#pragma unroll
                for (int nf = 0; nf < 6; nf++) {
                    int bq = nf >> 1, o = (nf & 1) * 2;
                    MMA_BF16(acc[mf][nf], ah[mf], b[bq][o], b[bq][o + 1]);
                    MMA_BF16(acc[mf][nf], al[mf], b[bq][o], b[bq][o + 1]);
                }
#pragma unroll
            for (int bq = 0; bq < 3; bq++) {
                uint32_t bd = st + ST_BL + (brow + bq * 16) * 80 + (kk + bcol8) * 2;
                LDMATRIX_X4(b[bq][0], b[bq][1], b[bq][2], b[bq][3], bd);
            }
#pragma unroll
            for (int mf = 0; mf < 2; mf++)
#pragma unroll
                for (int nf = 0; nf < 6; nf++) {
                    int bq = nf >> 1, o = (nf & 1) * 2;
                    MMA_BF16(acc[mf][nf], ah[mf], b[bq][o], b[bq][o + 1]);
                }
        }
    };

    loadB(0, 0);
    loadA(0);
    storeA(0);
    CP_WAIT0();
    __syncthreads();
    for (int c = 0; c < KCHUNKS; ++c) {
        int s = c & 1;
        if (c < KCHUNKS - 1) { loadB(c + 1, s ^ 1); loadA(c + 1); }
        compute(s);
        if (c < KCHUNKS - 1) {
            storeA(s ^ 1);
            CP_WAIT0();
            __syncthreads();
        }
    }

#pragma unroll
    for (int mf = 0; mf < 2; mf++) {
        int r0 = bm + wm * 32 + mf * 16 + (lane >> 2);
#pragma unroll
        for (int nf = 0; nf < 6; nf++) {
            int col = bn + wn * 48 + nf * 8 + (lane & 3) * 2;
            float2 v0 = make_float2(acc[mf][nf][0] + g_bias[col],
                                    acc[mf][nf][1] + g_bias[col + 1]);
            float2 v1 = make_float2(acc[mf][nf][2] + g_bias[col],
                                    acc[mf][nf][3] + g_bias[col + 1]);
            *reinterpret_cast<float2*>(g_Y + (size_t)r0 * NPAD + col) = v0;
            *reinterpret_cast<float2*>(g_Y + (size_t)(r0 + 8) * NPAD + col) = v1;
        }
    }
}

// ----------------------------- epilogue ------------------------------------
__global__ __launch_bounds__(256) void epilogue_kernel(float* __restrict__ out) {
    const int warp = threadIdx.x >> 5;
    const int lane = threadIdx.x & 31;
    const int row  = blockIdx.x * 8 + warp;

    __shared__ float sY[8][352];           // 348 used, row 1408B (16B aligned)
    __shared__ float sP[8][288];           // staged Plc for coalesced writes

    // vectorized g_Y row load: 87 float4 = 348 floats
    {
        const float4* yr4 = reinterpret_cast<const float4*>(g_Y + (size_t)row * NPAD);
        float4* sy4 = reinterpret_cast<float4*>(sY[warp]);
#pragma unroll
        for (int j = lane; j < 87; j += 32) sy4[j] = yr4[j];
    }
    __syncwarp();
    const float* s = sY[warp];

    float y0v = (lane < NCLS) ? s[lane] : -INFINITY;
    float m = y0v;
#pragma unroll
    for (int o = 16; o; o >>= 1) m = fmaxf(m, __shfl_xor_sync(0xFFFFFFFFu, m, o));
    float e = (lane < NCLS) ? expf(y0v - m) : 0.f;
    float ssum = e;
#pragma unroll
    for (int o = 16; o; o >>= 1) ssum += __shfl_xor_sync(0xFFFFFFFFu, ssum, o);
    float Pc = e / ssum;

    float best = -1.f, sec = -1.f;
    int bestk = 0;
    if (lane < NCLS) {
        const float* yc = s + 12 + lane * NCLU;
        float mc = -INFINITY;
#pragma unroll
        for (int k = 0; k < NCLU; k++) mc = fmaxf(mc, yc[k]);
        float sc = 0.f;
#pragma unroll
        for (int k = 0; k < NCLU; k++) sc += expf(yc[k] - mc);
        float inv = Pc / sc;
#pragma unroll
        for (int k = 0; k < NCLU; k++) {
            float p = expf(yc[k] - mc) * inv;
            sP[warp][k * NCLS + lane] = p;
            if (p > best) { sec = best; best = p; bestk = k; }
            else if (p > sec) sec = p;
        }
    }
    __syncwarp();

    // coalesced Plc writes: 72 float4 per row
    {
        const float4* sp4 = reinterpret_cast<const float4*>(sP[warp]);
        float4* po4 = reinterpret_cast<float4*>(out + PLC_OFF + (size_t)row * (NCLU * NCLS));
#pragma unroll
        for (int j = lane; j < 72; j += 32) po4[j] = sp4[j];
    }

    // argmax with first-flat-index tie-break
    float bv = best;
    int bi = bestk * NCLS + lane;
#pragma unroll
    for (int o = 16; o; o >>= 1) {
        float ov = __shfl_xor_sync(0xFFFFFFFFu, bv, o);
        int   oi = __shfl_xor_sync(0xFFFFFFFFu, bi, o);
        if (ov > bv || (ov == bv && oi < bi)) { bv = ov; bi = oi; }
    }
    const int ic = bi % NCLS;

    // top-2 across warp for uncertainty flag
    float t1 = best, t2 = sec;
#pragma unroll
    for (int o = 16; o; o >>= 1) {
        float o1 = __shfl_xor_sync(0xFFFFFFFFu, t1, o);
        float o2 = __shfl_xor_sync(0xFFFFFFFFu, t2, o);
        if (o1 > t1) { t2 = fmaxf(t1, o2); t1 = o1; }
        else         { t2 = fmaxf(t2, o1); }
    }
    if (lane == 0 && (t1 - t2) < 3e-4f * t1) {
        int p = atomicAdd(&g_flagcnt, 1);
        g_flagrows[p] = row;
    }

    if (lane < NCLS) out[Y0_OFF + (size_t)row * NCLS + lane] = s[lane];
    if (lane < NCLU) out[Y1_OFF + (size_t)row * NCLU + lane] = s[12 + ic * NCLU + lane];
    if (lane < NDIM) out[Y2_OFF + (size_t)row * NDIM + lane] = s[300 + ic * NDIM + lane];
}

// ----------------------------- fp32 exact fixup ----------------------------
// 1024 threads: 4 k-quarters (512 k each) x 256 column-slots.
__global__ __launch_bounds__(1024) void fixup_kernel(const float* __restrict__ x,
                                                     float* __restrict__ out) {
    __shared__ float sx[N0];
    __shared__ float part[4][NCOL];
    __shared__ float sy[NCOL];
    __shared__ float sPc[NCLS];
    __shared__ float sBP[NCLS];
    __shared__ int   sBK[NCLS];
    const int tid = threadIdx.x;
    const int q   = tid >> 8;          // k-quarter 0..3
    const int cc  = tid & 255;         // column slot
    const int cnt = g_flagcnt;

    for (int f = blockIdx.x; f < cnt; f += gridDim.x) {
        const int row = g_flagrows[f];
        { // load x row (2048 floats / 1024 threads = 2 each)
            float2 v = *reinterpret_cast<const float2*>(x + (size_t)row * N0 + tid * 2);
            sx[tid * 2] = v.x; sx[tid * 2 + 1] = v.y;
        }
        __syncthreads();
        for (int col = cc; col < NCOL; col += 256) {
            float acc = 0.f;
            const float* w = g_Wt + (size_t)(q * 512) * NPAD + col;
            const float* xp = sx + q * 512;
#pragma unroll 8
            for (int k = 0; k < 512; k++) acc += xp[k] * w[(size_t)k * NPAD];
            part[q][col] = acc;
        }
        __syncthreads();
        if (tid < NCOL)
            sy[tid] = part[0][tid] + part[1][tid] + part[2][tid] + part[3][tid] + g_bias[tid];
        __syncthreads();
        if (tid == 0) {
            float mm = -INFINITY;
            for (int c = 0; c < NCLS; c++) mm = fmaxf(mm, sy[c]);
            float ss = 0.f;
            for (int c = 0; c < NCLS; c++) ss += expf(sy[c] - mm);
            for (int c = 0; c < NCLS; c++) sPc[c] = expf(sy[c] - mm) / ss;
        }
        __syncthreads();
        if (tid < NCLS) {
            const float* yc = sy + 12 + tid * NCLU;
            float mc = -INFINITY;
            for (int k = 0; k < NCLU; k++) mc = fmaxf(mc, yc[k]);
            float sc = 0.f;
            for (int k = 0; k < NCLU; k++) sc += expf(yc[k] - mc);
            float inv = sPc[tid] / sc;
            float b = -1.f; int bk = 0;
            for (int k = 0; k < NCLU; k++) {
                float p = expf(yc[k] - mc) * inv;
                if (p > b) { b = p; bk = k; }
            }
            sBP[tid] = b; sBK[tid] = bk;
        }
        __syncthreads();
        if (tid == 0) {
            float bp = -1.f; int bi = 0x7FFFFFFF;
            for (int c = 0; c < NCLS; c++) {
                int flat = sBK[c] * NCLS + c;
                if (sBP[c] > bp || (sBP[c] == bp && flat < bi)) { bp = sBP[c]; bi = flat; }
            }
            int ic = bi % NCLS;
            for (int k = 0; k < NCLU; k++)
                out[Y1_OFF + (size_t)row * NCLU + k] = sy[12 + ic * NCLU + k];
            for (int n = 0; n < NDIM; n++)
                out[Y2_OFF + (size_t)row * NDIM + n] = sy[300 + ic * NDIM + n];
        }
        __syncthreads();
    }
}

// ============================================================================
extern "C" void kernel_launch(void* const* d_in, const int* in_sizes, int n_in,
                              void* d_out, int out_size) {
    const float* x    = (const float*)d_in[0];
    const float* Wfc  = (const float*)d_in[1];
    const float* bfc  = (const float*)d_in[2];
    const float* Wbin = (const float*)d_in[3];
    const float* bbin = (const float*)d_in[4];
    const float* Wres = (const float*)d_in[5];
    const float* bres = (const float*)d_in[6];
    float* out = (float*)d_out;

    static bool attr_set = false;
    if (!attr_set) {
        cudaFuncSetAttribute(gemm_kernel, cudaFuncAttributeMaxDynamicSharedMemorySize, SMEM_TOTAL);
        attr_set = true;
    }

    int pack_tasks = N0 * NPAD + NPAD * (N0 / 8);
    pack_kernel<<<(pack_tasks + 255) / 256, 256>>>(Wfc, bfc, Wbin, bbin, Wres, bres);

    gemm_kernel<<<dim3(NPAD / BN, B_ROWS / BM), THREADS, SMEM_TOTAL>>>(x);

    epilogue_kernel<<<B_ROWS / 8, 256>>>(out);

    fixup_kernel<<<96, 1024>>>(x, out);
}

// round 9
// speedup vs baseline: 2.4713x; 1.0810x over previous
#include <cuda_runtime.h>
#include <cuda_bf16.h>
#include <math.h>
#include <stdint.h>

#define B_ROWS 16384
#define N0     2048
#define NCLS   12
#define NCLU   24
#define NDIM   4
#define NCOL   348
#define NPAD   384

// GEMM tiling
#define BM 128
#define BN 96
#define BK 32
#define THREADS 256
#define KCHUNKS (N0 / BK)     // 64

// smem stage layout (bytes); rows padded to 40 bf16 (80B) => conflict-free ldmatrix
#define ST_AH 0
#define ST_AL 10240           // 128*80
#define ST_BH 20480
#define ST_BL 28160           // + 96*80
#define STAGE 35840
#define SMEM_TOTAL (2 * STAGE)  // 71680

// ----------------------------- device scratch ------------------------------
__device__ float g_Wt[N0 * NPAD];                  // fp32 packed weights (fixup)
__device__ float g_bias[NPAD];
__device__ float g_Y[(size_t)B_ROWS * NPAD];       // GEMM output
__device__ __align__(16) __nv_bfloat16 g_Bh[NPAD * N0];  // W^T hi, [n][k]
__device__ __align__(16) __nv_bfloat16 g_Bl[NPAD * N0];  // W^T lo, [n][k]
__device__ int g_flagcnt;
__device__ int g_flagrows[B_ROWS];

// output layout (tuple concat) — validated in round 1
#define Y0_OFF   0
#define Y1_OFF   ((size_t)B_ROWS * 12)
#define Y2_OFF   ((size_t)B_ROWS * 36)
#define PLC_OFF  ((size_t)B_ROWS * 40)

// ----------------------------- PTX helpers ---------------------------------
__device__ __forceinline__ uint32_t smem_u32(const void* p) {
    uint32_t a;
    asm("{ .reg .u64 t; cvta.to.shared.u64 t, %1; cvt.u32.u64 %0, t; }" : "=r"(a) : "l"(p));
    return a;
}
#define CP_ASYNC16(dst, src) \
    asm volatile("cp.async.cg.shared.global [%0], [%1], 16;" :: "r"(dst), "l"(src))
#define CP_COMMIT() asm volatile("cp.async.commit_group;" ::: "memory")
#define CP_WAIT0()  asm volatile("cp.async.wait_group 0;" ::: "memory")

#define LDMATRIX_X4(r0, r1, r2, r3, addr) \
    asm volatile("ldmatrix.sync.aligned.m8n8.x4.shared.b16 {%0,%1,%2,%3}, [%4];" \
                 : "=r"(r0), "=r"(r1), "=r"(r2), "=r"(r3) : "r"(addr))

#define MMA_BF16(d, a, b0, b1) \
    asm volatile("mma.sync.aligned.m16n8k16.row.col.f32.bf16.bf16.f32 " \
                 "{%0,%1,%2,%3}, {%4,%5,%6,%7}, {%8,%9}, {%0,%1,%2,%3};" \
                 : "+f"((d)[0]), "+f"((d)[1]), "+f"((d)[2]), "+f"((d)[3]) \
                 : "r"((a)[0]), "r"((a)[1]), "r"((a)[2]), "r"((a)[3]), "r"(b0), "r"(b1))

// ----------------------------- packing -------------------------------------
__device__ __forceinline__ float colval(int j, int k, const float* Wfc,
                                        const float* Wbin, const float* Wres) {
    if (j < 12) return Wfc[k * NCLS + j];
    if (j < 300) { int t = j - 12, c = t / NCLU, kk = t - c * NCLU;
                   return Wbin[((size_t)c * N0 + k) * NCLU + kk]; }
    if (j < NCOL) { int t = j - 300, c = t / NDIM, n = t - c * NDIM;
                    return Wres[((size_t)c * N0 + k) * NDIM + n]; }
    return 0.f;
}

__global__ void pack_kernel(const float* __restrict__ Wfc,  const float* __restrict__ bfc,
                            const float* __restrict__ Wbin, const float* __restrict__ bbin,
                            const float* __restrict__ Wres, const float* __restrict__ bres) {
    int idx = blockIdx.x * blockDim.x + threadIdx.x;
    if (idx == 0) g_flagcnt = 0;
    if (idx < N0 * NPAD) {            // g_Wt [k][j], coalesced in j
        int k = idx / NPAD, j = idx - k * NPAD;
        g_Wt[idx] = colval(j, k, Wfc, Wbin, Wres);
    }
    if (idx < NPAD) {
        float bv = 0.f;
        if (idx < 12) bv = bfc[idx];
        else if (idx < 300) { int t = idx - 12, c = t / NCLU, kk = t - c * NCLU; bv = bbin[c * NCLU + kk]; }
        else if (idx < NCOL) { int t = idx - 300, c = t / NDIM, n = t - c * NDIM; bv = bres[c * NDIM + n]; }
        g_bias[idx] = bv;
    }
    // region 2: bf16 hi/lo transposed weights [n][k], 8 k per thread
    int t = idx - N0 * NPAD;
    if (t >= 0 && t < NPAD * (N0 / 8)) {
        int n = t / (N0 / 8);
        int k0 = (t % (N0 / 8)) * 8;
        float v[8];
#pragma unroll
        for (int e = 0; e < 8; e++) v[e] = colval(n, k0 + e, Wfc, Wbin, Wres);
        uint32_t hp[4], lp[4];
#pragma unroll
        for (int i = 0; i < 4; i++) {
            __nv_bfloat162 h2 = __floats2bfloat162_rn(v[2*i], v[2*i+1]);
            float r0 = v[2*i]   - __bfloat162float(h2.x);
            float r1 = v[2*i+1] - __bfloat162float(h2.y);
            __nv_bfloat162 l2 = __floats2bfloat162_rn(r0, r1);
            hp[i] = *reinterpret_cast<uint32_t*>(&h2);
            lp[i] = *reinterpret_cast<uint32_t*>(&l2);
        }
        *reinterpret_cast<uint4*>(&g_Bh[n * N0 + k0]) = make_uint4(hp[0], hp[1], hp[2], hp[3]);
        *reinterpret_cast<uint4*>(&g_Bl[n * N0 + k0]) = make_uint4(lp[0], lp[1], lp[2], lp[3]);
    }
}

// ----------------------------- mma.sync GEMM -------------------------------
// Y[16384][384] = x @ W (+bias), 3-term bf16 split, fp32 accum.
__global__ __launch_bounds__(THREADS) void gemm_kernel(const float* __restrict__ x) {
    extern __shared__ char smem[];
    const uint32_t sb = smem_u32(smem);
    const int tid  = threadIdx.x;
    const int lane = tid & 31;
    const int wid  = tid >> 5;
    const int wm   = wid >> 1;          // 0..3
    const int wn   = wid & 1;           // 0..1
    const int bm   = blockIdx.y * BM;
    const int bn   = blockIdx.x * BN;

    float acc[2][6][4];
#pragma unroll
    for (int i = 0; i < 2; i++)
#pragma unroll
        for (int j = 0; j < 6; j++)
#pragma unroll
            for (int q = 0; q < 4; q++) acc[i][j][q] = 0.f;

    auto loadB = [&](int c, int s) {
#pragma unroll
        for (int it = 0; it < 3; ++it) {
            int g = tid + it * 256;                 // 0..767
            int half = (g >= 384);
            int idx2 = g - half * 384;
            int row = idx2 >> 2, seg = idx2 & 3;
            const __nv_bfloat16* src = (half ? g_Bl : g_Bh)
                                     + (size_t)(bn + row) * N0 + c * BK + seg * 8;
            uint32_t dst = sb + s * STAGE + (half ? ST_BL : ST_BH) + row * 80 + seg * 16;
            CP_ASYNC16(dst, src);
        }
        CP_COMMIT();
    };
    float4 areg[4];
    auto loadA = [&](int c) {
#pragma unroll
        for (int it = 0; it < 4; ++it) {
            int idx2 = tid + it * 256;              // 0..1023
            int row = idx2 >> 3, seg = idx2 & 7;
            areg[it] = *reinterpret_cast<const float4*>(
                x + (size_t)(bm + row) * N0 + c * BK + seg * 4);
        }
    };
    auto storeA = [&](int s) {
#pragma unroll
        for (int it = 0; it < 4; ++it) {
            int idx2 = tid + it * 256;
            int row = idx2 >> 3, seg = idx2 & 7;
            float v[4] = {areg[it].x, areg[it].y, areg[it].z, areg[it].w};
            uint32_t hp[2], lp[2];
#pragma unroll
            for (int i = 0; i < 2; i++) {
                __nv_bfloat162 h2 = __floats2bfloat162_rn(v[2*i], v[2*i+1]);
                float r0 = v[2*i]   - __bfloat162float(h2.x);
                float r1 = v[2*i+1] - __bfloat162float(h2.y);
                __nv_bfloat162 l2 = __floats2bfloat162_rn(r0, r1);
                hp[i] = *reinterpret_cast<uint32_t*>(&h2);
                lp[i] = *reinterpret_cast<uint32_t*>(&l2);
            }
            char* base = smem + s * STAGE;
            *reinterpret_cast<uint2*>(base + ST_AH + row * 80 + seg * 8) = make_uint2(hp[0], hp[1]);
            *reinterpret_cast<uint2*>(base + ST_AL + row * 80 + seg * 8) = make_uint2(lp[0], lp[1]);
        }
    };

    auto compute = [&](int s) {
        const uint32_t st = sb + s * STAGE;
        const int arow = wm * 32 + (lane & 15);
        const int acol8 = (lane >> 4) * 8;
        const int brow = wn * 48 + ((lane >> 4) & 1) * 8 + (lane & 7);
        const int bcol8 = ((lane >> 3) & 1) * 8;
#pragma unroll
        for (int kk = 0; kk < BK; kk += 16) {
            uint32_t ah[2][4], al[2][4], b[3][4];
#pragma unroll
            for (int mf = 0; mf < 2; mf++) {
                uint32_t ad = st + ST_AH + (arow + mf * 16) * 80 + (kk + acol8) * 2;
                LDMATRIX_X4(ah[mf][0], ah[mf][1], ah[mf][2], ah[mf][3], ad);
                uint32_t adl = st + ST_AL + (arow + mf * 16) * 80 + (kk + acol8) * 2;
                LDMATRIX_X4(al[mf][0], al[mf][1], al[mf][2], al[mf][3], adl);
            }
#pragma unroll
            for (int bq = 0; bq < 3; bq++) {
                uint32_t bd = st + ST_BH + (brow + bq * 16) * 80 + (kk + bcol8) * 2;
                LDMATRIX_X4(b[bq][0], b[bq][1], b[bq][2], b[bq][3], bd);
            }
#pragma unroll
            for (int mf = 0; mf < 2; mf++)
#pragma unroll
                for (int nf = 0; nf < 6; nf++) {
                    int bq = nf >> 1, o = (nf & 1) * 2;
                    MMA_BF16(acc[mf][nf], ah[mf], b[bq][o], b[bq][o + 1]);
                    MMA_BF16(acc[mf][nf], al[mf], b[bq][o], b[bq][o + 1]);
                }
#pragma unroll
            for (int bq = 0; bq < 3; bq++) {
                uint32_t bd = st + ST_BL + (brow + bq * 16) * 80 + (kk + bcol8) * 2;
                LDMATRIX_X4(b[bq][0], b[bq][1], b[bq][2], b[bq][3], bd);
            }
#pragma unroll
            for (int mf = 0; mf < 2; mf++)
#pragma unroll
                for (int nf = 0; nf < 6; nf++) {
                    int bq = nf >> 1, o = (nf & 1) * 2;
                    MMA_BF16(acc[mf][nf], ah[mf], b[bq][o], b[bq][o + 1]);
                }
        }
    };

    loadB(0, 0);
    loadA(0);
    storeA(0);
    CP_WAIT0();
    __syncthreads();
    for (int c = 0; c < KCHUNKS; ++c) {
        int s = c & 1;
        if (c < KCHUNKS - 1) { loadB(c + 1, s ^ 1); loadA(c + 1); }
        compute(s);
        if (c < KCHUNKS - 1) {
            storeA(s ^ 1);
            CP_WAIT0();
            __syncthreads();
        }
    }

#pragma unroll
    for (int mf = 0; mf < 2; mf++) {
        int r0 = bm + wm * 32 + mf * 16 + (lane >> 2);
#pragma unroll
        for (int nf = 0; nf < 6; nf++) {
            int col = bn + wn * 48 + nf * 8 + (lane & 3) * 2;
            float2 v0 = make_float2(acc[mf][nf][0] + g_bias[col],
                                    acc[mf][nf][1] + g_bias[col + 1]);
            float2 v1 = make_float2(acc[mf][nf][2] + g_bias[col],
                                    acc[mf][nf][3] + g_bias[col + 1]);
            *reinterpret_cast<float2*>(g_Y + (size_t)r0 * NPAD + col) = v0;
            *reinterpret_cast<float2*>(g_Y + (size_t)(r0 + 8) * NPAD + col) = v1;
        }
    }
}

// ----------------------------- epilogue ------------------------------------
__global__ __launch_bounds__(256) void epilogue_kernel(float* __restrict__ out) {
    const int warp = threadIdx.x >> 5;
    const int lane = threadIdx.x & 31;
    const int row  = blockIdx.x * 8 + warp;

    __shared__ float sY[8][352];           // 348 used, row 1408B (16B aligned)
    __shared__ float sP[8][288];           // staged Plc for coalesced writes

    // vectorized g_Y row load: 87 float4 = 348 floats
    {
        const float4* yr4 = reinterpret_cast<const float4*>(g_Y + (size_t)row * NPAD);
        float4* sy4 = reinterpret_cast<float4*>(sY[warp]);
#pragma unroll
        for (int j = lane; j < 87; j += 32) sy4[j] = yr4[j];
    }
    __syncwarp();
    const float* s = sY[warp];

    float y0v = (lane < NCLS) ? s[lane] : -INFINITY;
    float m = y0v;
#pragma unroll
    for (int o = 16; o; o >>= 1) m = fmaxf(m, __shfl_xor_sync(0xFFFFFFFFu, m, o));
    float e = (lane < NCLS) ? expf(y0v - m) : 0.f;
    float ssum = e;
#pragma unroll
    for (int o = 16; o; o >>= 1) ssum += __shfl_xor_sync(0xFFFFFFFFu, ssum, o);
    float Pc = e / ssum;

    float best = -1.f, sec = -1.f;
    int bestk = 0;
    if (lane < NCLS) {
        const float* yc = s + 12 + lane * NCLU;
        float mc = -INFINITY;
#pragma unroll
        for (int k = 0; k < NCLU; k++) mc = fmaxf(mc, yc[k]);
        float sc = 0.f;
#pragma unroll
        for (int k = 0; k < NCLU; k++) sc += expf(yc[k] - mc);
        float inv = Pc / sc;
#pragma unroll
        for (int k = 0; k < NCLU; k++) {
            float p = expf(yc[k] - mc) * inv;
            sP[warp][k * NCLS + lane] = p;
            if (p > best) { sec = best; best = p; bestk = k; }
            else if (p > sec) sec = p;
        }
    }
    __syncwarp();

    // coalesced Plc writes: 72 float4 per row
    {
        const float4* sp4 = reinterpret_cast<const float4*>(sP[warp]);
        float4* po4 = reinterpret_cast<float4*>(out + PLC_OFF + (size_t)row * (NCLU * NCLS));
#pragma unroll
        for (int j = lane; j < 72; j += 32) po4[j] = sp4[j];
    }

    // argmax with first-flat-index tie-break
    float bv = best;
    int bi = bestk * NCLS + lane;
#pragma unroll
    for (int o = 16; o; o >>= 1) {
        float ov = __shfl_xor_sync(0xFFFFFFFFu, bv, o);
        int   oi = __shfl_xor_sync(0xFFFFFFFFu, bi, o);
        if (ov > bv || (ov == bv && oi < bi)) { bv = ov; bi = oi; }
    }
    const int ic = bi % NCLS;

    // cross-class top-2 (per-lane best is per-class max; flips within a class
    // don't change ic, so only the cross-class gap matters)
    float t1 = best, t2 = sec;
#pragma unroll
    for (int o = 16; o; o >>= 1) {
        float o1 = __shfl_xor_sync(0xFFFFFFFFu, t1, o);
        float o2 = __shfl_xor_sync(0xFFFFFFFFu, t2, o);
        if (o1 > t1) { t2 = fmaxf(t1, o2); t1 = o1; }
        else         { t2 = fmaxf(t2, o1); }
    }
    if (lane == 0 && (t1 - t2) < 1.2e-4f * t1) {
        int p = atomicAdd(&g_flagcnt, 1);
        g_flagrows[p] = row;
    }

    if (lane < NCLS) out[Y0_OFF + (size_t)row * NCLS + lane] = s[lane];
    if (lane < NCLU) out[Y1_OFF + (size_t)row * NCLU + lane] = s[12 + ic * NCLU + lane];
    if (lane < NDIM) out[Y2_OFF + (size_t)row * NDIM + lane] = s[300 + ic * NDIM + lane];
}

// ----------------------------- fp32 exact fixup ----------------------------
// 1024 threads: 4 k-quarters (512 k each) x 256 column-slots.
// Launched with a wide grid so each block handles ~1 flagged row.
__global__ __launch_bounds__(1024) void fixup_kernel(const float* __restrict__ x,
                                                     float* __restrict__ out) {
    __shared__ float sx[N0];
    __shared__ float part[4][NCOL];
    __shared__ float sy[NCOL];
    __shared__ float sPc[NCLS];
    __shared__ float sBP[NCLS];
    __shared__ int   sBK[NCLS];
    const int tid = threadIdx.x;
    const int q   = tid >> 8;          // k-quarter 0..3
    const int cc  = tid & 255;         // column slot
    const int cnt = g_flagcnt;

    for (int f = blockIdx.x; f < cnt; f += gridDim.x) {
        const int row = g_flagrows[f];
        { // load x row (2048 floats / 1024 threads = 2 each)
            float2 v = *reinterpret_cast<const float2*>(x + (size_t)row * N0 + tid * 2);
            sx[tid * 2] = v.x; sx[tid * 2 + 1] = v.y;
        }
        __syncthreads();
        for (int col = cc; col < NCOL; col += 256) {
            float acc = 0.f;
            const float* w = g_Wt + (size_t)(q * 512) * NPAD + col;
            const float* xp = sx + q * 512;
#pragma unroll 16
            for (int k = 0; k < 512; k++) acc += xp[k] * w[(size_t)k * NPAD];
            part[q][col] = acc;
        }
        __syncthreads();
        if (tid < NCOL)
            sy[tid] = part[0][tid] + part[1][tid] + part[2][tid] + part[3][tid] + g_bias[tid];
        __syncthreads();
        if (tid == 0) {
            float mm = -INFINITY;
            for (int c = 0; c < NCLS; c++) mm = fmaxf(mm, sy[c]);
            float ss = 0.f;
            for (int c = 0; c < NCLS; c++) ss += expf(sy[c] - mm);
            for (int c = 0; c < NCLS; c++) sPc[c] = expf(sy[c] - mm) / ss;
        }
        __syncthreads();
        if (tid < NCLS) {
            const float* yc = sy + 12 + tid * NCLU;
            float mc = -INFINITY;
            for (int k = 0; k < NCLU; k++) mc = fmaxf(mc, yc[k]);
            float sc = 0.f;
            for (int k = 0; k < NCLU; k++) sc += expf(yc[k] - mc);
            float inv = sPc[tid] / sc;
            float b = -1.f; int bk = 0;
            for (int k = 0; k < NCLU; k++) {
                float p = expf(yc[k] - mc) * inv;
                if (p > b) { b = p; bk = k; }
            }
            sBP[tid] = b; sBK[tid] = bk;
        }
        __syncthreads();
        if (tid == 0) {
            float bp = -1.f; int bi = 0x7FFFFFFF;
            for (int c = 0; c < NCLS; c++) {
                int flat = sBK[c] * NCLS + c;
                if (sBP[c] > bp || (sBP[c] == bp && flat < bi)) { bp = sBP[c]; bi = flat; }
            }
            int ic = bi % NCLS;
            for (int k = 0; k < NCLU; k++)
                out[Y1_OFF + (size_t)row * NCLU + k] = sy[12 + ic * NCLU + k];
            for (int n = 0; n < NDIM; n++)
                out[Y2_OFF + (size_t)row * NDIM + n] = sy[300 + ic * NDIM + n];
        }
        __syncthreads();
    }
}

// ============================================================================
extern "C" void kernel_launch(void* const* d_in, const int* in_sizes, int n_in,
                              void* d_out, int out_size) {
    const float* x    = (const float*)d_in[0];
    const float* Wfc  = (const float*)d_in[1];
    const float* bfc  = (const float*)d_in[2];
    const float* Wbin = (const float*)d_in[3];
    const float* bbin = (const float*)d_in[4];
    const float* Wres = (const float*)d_in[5];
    const float* bres = (const float*)d_in[6];
    float* out = (float*)d_out;

    static bool attr_set = false;
    if (!attr_set) {
        cudaFuncSetAttribute(gemm_kernel, cudaFuncAttributeMaxDynamicSharedMemorySize, SMEM_TOTAL);
        attr_set = true;
    }

    int pack_tasks = N0 * NPAD + NPAD * (N0 / 8);
    pack_kernel<<<(pack_tasks + 255) / 256, 256>>>(Wfc, bfc, Wbin, bbin, Wres, bres);

    gemm_kernel<<<dim3(NPAD / BN, B_ROWS / BM), THREADS, SMEM_TOTAL>>>(x);

    epilogue_kernel<<<B_ROWS / 8, 256>>>(out);

    // wide grid: ~1 flagged row per block; surplus blocks exit immediately
    fixup_kernel<<<1024, 1024>>>(x, out);
}

// round 11
// speedup vs baseline: 2.7538x; 1.1143x over previous
#include <cuda_runtime.h>
#include <cuda_bf16.h>
#include <math.h>
#include <stdint.h>

#define B_ROWS 16384
#define N0     2048
#define NCLS   12
#define NCLU   24
#define NDIM   4
#define NCOL   348
#define NPAD   384

// GEMM tiling
#define BM 128
#define BN 96
#define BK 32
#define THREADS 256
#define KCHUNKS (N0 / BK)     // 64

// smem stage layout (bytes); rows padded to 40 bf16 (80B) => conflict-free ldmatrix
#define ST_AH 0
#define ST_AL 10240           // 128*80
#define ST_BH 20480
#define ST_BL 28160           // + 96*80
#define STAGE 35840
#define SMEM_TOTAL (2 * STAGE)  // 71680

#define FLAG_THRESH 1.2e-4f

// ----------------------------- device scratch ------------------------------
__device__ float g_Wt[N0 * NPAD];                  // fp32 packed weights [k][j]
__device__ float g_Wc[NCOL * N0];                  // fp32 packed weights [j][k] (fixup)
__device__ float g_bias[NPAD];
__device__ float g_Y[(size_t)B_ROWS * NPAD];       // GEMM output
__device__ __align__(16) __nv_bfloat16 g_Bh[NPAD * N0];  // W^T hi, [n][k]
__device__ __align__(16) __nv_bfloat16 g_Bl[NPAD * N0];  // W^T lo, [n][k]
__device__ int g_flagcnt;
__device__ int g_flagrows[B_ROWS];                 // row | (candidate mask << 14)

// output layout (tuple concat) — validated in round 1
#define Y0_OFF   0
#define Y1_OFF   ((size_t)B_ROWS * 12)
#define Y2_OFF   ((size_t)B_ROWS * 36)
#define PLC_OFF  ((size_t)B_ROWS * 40)

// ----------------------------- PTX helpers ---------------------------------
__device__ __forceinline__ uint32_t smem_u32(const void* p) {
    uint32_t a;
    asm("{ .reg .u64 t; cvta.to.shared.u64 t, %1; cvt.u32.u64 %0, t; }" : "=r"(a) : "l"(p));
    return a;
}
#define CP_ASYNC16(dst, src) \
    asm volatile("cp.async.cg.shared.global [%0], [%1], 16;" :: "r"(dst), "l"(src))
#define CP_COMMIT() asm volatile("cp.async.commit_group;" ::: "memory")
#define CP_WAIT0()  asm volatile("cp.async.wait_group 0;" ::: "memory")

#define LDMATRIX_X4(r0, r1, r2, r3, addr) \
    asm volatile("ldmatrix.sync.aligned.m8n8.x4.shared.b16 {%0,%1,%2,%3}, [%4];" \
                 : "=r"(r0), "=r"(r1), "=r"(r2), "=r"(r3) : "r"(addr))

#define MMA_BF16(d, a, b0, b1) \
    asm volatile("mma.sync.aligned.m16n8k16.row.col.f32.bf16.bf16.f32 " \
                 "{%0,%1,%2,%3}, {%4,%5,%6,%7}, {%8,%9}, {%0,%1,%2,%3};" \
                 : "+f"((d)[0]), "+f"((d)[1]), "+f"((d)[2]), "+f"((d)[3]) \
                 : "r"((a)[0]), "r"((a)[1]), "r"((a)[2]), "r"((a)[3]), "r"(b0), "r"(b1))

// ----------------------------- packing -------------------------------------
__device__ __forceinline__ float colval(int j, int k, const float* Wfc,
                                        const float* Wbin, const float* Wres) {
    if (j < 12) return Wfc[k * NCLS + j];
    if (j < 300) { int t = j - 12, c = t / NCLU, kk = t - c * NCLU;
                   return Wbin[((size_t)c * N0 + k) * NCLU + kk]; }
    if (j < NCOL) { int t = j - 300, c = t / NDIM, n = t - c * NDIM;
                    return Wres[((size_t)c * N0 + k) * NDIM + n]; }
    return 0.f;
}

#define PACK_R1 (N0 * NPAD)                 // g_Wt tasks
#define PACK_R2 (NPAD * (N0 / 8))           // bf16 hi/lo tasks
#define PACK_R3 (NCOL * (N0 / 4))           // g_Wc float4 tasks
#define PACK_TASKS (PACK_R1 + PACK_R2 + PACK_R3)

__global__ void pack_kernel(const float* __restrict__ Wfc,  const float* __restrict__ bfc,
                            const float* __restrict__ Wbin, const float* __restrict__ bbin,
                            const float* __restrict__ Wres, const float* __restrict__ bres) {
    int idx = blockIdx.x * blockDim.x + threadIdx.x;
    if (idx == 0) g_flagcnt = 0;
    if (idx < PACK_R1) {              // g_Wt [k][j], coalesced in j
        int k = idx / NPAD, j = idx - k * NPAD;
        g_Wt[idx] = colval(j, k, Wfc, Wbin, Wres);
    }
    if (idx < NPAD) {
        float bv = 0.f;
        if (idx < 12) bv = bfc[idx];
        else if (idx < 300) { int t = idx - 12, c = t / NCLU, kk = t - c * NCLU; bv = bbin[c * NCLU + kk]; }
        else if (idx < NCOL) { int t = idx - 300, c = t / NDIM, n = t - c * NDIM; bv = bres[c * NDIM + n]; }
        g_bias[idx] = bv;
    }
    // region 2: bf16 hi/lo transposed weights [n][k], 8 k per thread
    int t = idx - PACK_R1;
    if (t >= 0 && t < PACK_R2) {
        int n = t / (N0 / 8);
        int k0 = (t % (N0 / 8)) * 8;
        float v[8];
#pragma unroll
        for (int e = 0; e < 8; e++) v[e] = colval(n, k0 + e, Wfc, Wbin, Wres);
        uint32_t hp[4], lp[4];
#pragma unroll
        for (int i = 0; i < 4; i++) {
            __nv_bfloat162 h2 = __floats2bfloat162_rn(v[2*i], v[2*i+1]);
            float r0 = v[2*i]   - __bfloat162float(h2.x);
            float r1 = v[2*i+1] - __bfloat162float(h2.y);
            __nv_bfloat162 l2 = __floats2bfloat162_rn(r0, r1);
            hp[i] = *reinterpret_cast<uint32_t*>(&h2);
            lp[i] = *reinterpret_cast<uint32_t*>(&l2);
        }
        *reinterpret_cast<uint4*>(&g_Bh[n * N0 + k0]) = make_uint4(hp[0], hp[1], hp[2], hp[3]);
        *reinterpret_cast<uint4*>(&g_Bl[n * N0 + k0]) = make_uint4(lp[0], lp[1], lp[2], lp[3]);
    }
    // region 3: column-major fp32 weights g_Wc[j][k], float4 per thread
    int t3 = idx - PACK_R1 - PACK_R2;
    if (t3 >= 0 && t3 < PACK_R3) {
        int col = t3 / (N0 / 4);
        int k0  = (t3 % (N0 / 4)) * 4;
        float4 v;
        v.x = colval(col, k0 + 0, Wfc, Wbin, Wres);
        v.y = colval(col, k0 + 1, Wfc, Wbin, Wres);
        v.z = colval(col, k0 + 2, Wfc, Wbin, Wres);
        v.w = colval(col, k0 + 3, Wfc, Wbin, Wres);
        *reinterpret_cast<float4*>(&g_Wc[col * N0 + k0]) = v;
    }
}

// ----------------------------- mma.sync GEMM -------------------------------
// Y[16384][384] = x @ W (+bias), 3-term bf16 split, fp32 accum.
__global__ __launch_bounds__(THREADS) void gemm_kernel(const float* __restrict__ x) {
    extern __shared__ char smem[];
    const uint32_t sb = smem_u32(smem);
    const int tid  = threadIdx.x;
    const int lane = tid & 31;
    const int wid  = tid >> 5;
    const int wm   = wid >> 1;          // 0..3
    const int wn   = wid & 1;           // 0..1
    const int bm   = blockIdx.y * BM;
    const int bn   = blockIdx.x * BN;

    float acc[2][6][4];
#pragma unroll
    for (int i = 0; i < 2; i++)
#pragma unroll
        for (int j = 0; j < 6; j++)
#pragma unroll
            for (int q = 0; q < 4; q++) acc[i][j][q] = 0.f;

    auto loadB = [&](int c, int s) {
#pragma unroll
        for (int it = 0; it < 3; ++it) {
            int g = tid + it * 256;                 // 0..767
            int half = (g >= 384);
            int idx2 = g - half * 384;
            int row = idx2 >> 2, seg = idx2 & 3;
            const __nv_bfloat16* src = (half ? g_Bl : g_Bh)
                                     + (size_t)(bn + row) * N0 + c * BK + seg * 8;
            uint32_t dst = sb + s * STAGE + (half ? ST_BL : ST_BH) + row * 80 + seg * 16;
            CP_ASYNC16(dst, src);
        }
        CP_COMMIT();
    };
    float4 areg[4];
    auto loadA = [&](int c) {
#pragma unroll
        for (int it = 0; it < 4; ++it) {
            int idx2 = tid + it * 256;              // 0..1023
            int row = idx2 >> 3, seg = idx2 & 7;
            areg[it] = *reinterpret_cast<const float4*>(
                x + (size_t)(bm + row) * N0 + c * BK + seg * 4);
        }
    };
    auto storeA = [&](int s) {
#pragma unroll
        for (int it = 0; it < 4; ++it) {
            int idx2 = tid + it * 256;
            int row = idx2 >> 3, seg = idx2 & 7;
            float v[4] = {areg[it].x, areg[it].y, areg[it].z, areg[it].w};
            uint32_t hp[2], lp[2];
#pragma unroll
            for (int i = 0; i < 2; i++) {
                __nv_bfloat162 h2 = __floats2bfloat162_rn(v[2*i], v[2*i+1]);
                float r0 = v[2*i]   - __bfloat162float(h2.x);
                float r1 = v[2*i+1] - __bfloat162float(h2.y);
                __nv_bfloat162 l2 = __floats2bfloat162_rn(r0, r1);
                hp[i] = *reinterpret_cast<uint32_t*>(&h2);
                lp[i] = *reinterpret_cast<uint32_t*>(&l2);
            }
            char* base = smem + s * STAGE;
            *reinterpret_cast<uint2*>(base + ST_AH + row * 80 + seg * 8) = make_uint2(hp[0], hp[1]);
            *reinterpret_cast<uint2*>(base + ST_AL + row * 80 + seg * 8) = make_uint2(lp[0], lp[1]);
        }
    };

    auto compute = [&](int s) {
        const uint32_t st = sb + s * STAGE;
        const int arow = wm * 32 + (lane & 15);
        const int acol8 = (lane >> 4) * 8;
        const int brow = wn * 48 + ((lane >> 4) & 1) * 8 + (lane & 7);
        const int bcol8 = ((lane >> 3) & 1) * 8;
#pragma unroll
        for (int kk = 0; kk < BK; kk += 16) {
            uint32_t ah[2][4], al[2][4], b[3][4];
#pragma unroll
            for (int mf = 0; mf < 2; mf++) {
                uint32_t ad = st + ST_AH + (arow + mf * 16) * 80 + (kk + acol8) * 2;
                LDMATRIX_X4(ah[mf][0], ah[mf][1], ah[mf][2], ah[mf][3], ad);
                uint32_t adl = st + ST_AL + (arow + mf * 16) * 80 + (kk + acol8) * 2;
                LDMATRIX_X4(al[mf][0], al[mf][1], al[mf][2], al[mf][3], adl);
            }
#pragma unroll
            for (int bq = 0; bq < 3; bq++) {
                uint32_t bd = st + ST_BH + (brow + bq * 16) * 80 + (kk + bcol8) * 2;
                LDMATRIX_X4(b[bq][0], b[bq][1], b[bq][2], b[bq][3], bd);
            }
#pragma unroll
            for (int mf = 0; mf < 2; mf++)
#pragma unroll
                for (int nf = 0; nf < 6; nf++) {
                    int bq = nf >> 1, o = (nf & 1) * 2;
                    MMA_BF16(acc[mf][nf], ah[mf], b[bq][o], b[bq][o + 1]);
                    MMA_BF16(acc[mf][nf], al[mf], b[bq][o], b[bq][o + 1]);
                }
#pragma unroll
            for (int bq = 0; bq < 3; bq++) {
                uint32_t bd = st + ST_BL + (brow + bq * 16) * 80 + (kk + bcol8) * 2;
                LDMATRIX_X4(b[bq][0], b[bq][1], b[bq][2], b[bq][3], bd);
            }
#pragma unroll
            for (int mf = 0; mf < 2; mf++)
#pragma unroll
                for (int nf = 0; nf < 6; nf++) {
                    int bq = nf >> 1, o = (nf & 1) * 2;
                    MMA_BF16(acc[mf][nf], ah[mf], b[bq][o], b[bq][o + 1]);
                }
        }
    };

    loadB(0, 0);
    loadA(0);
    storeA(0);
    CP_WAIT0();
    __syncthreads();
    for (int c = 0; c < KCHUNKS; ++c) {
        int s = c & 1;
        if (c < KCHUNKS - 1) { loadB(c + 1, s ^ 1); loadA(c + 1); }
        compute(s);
        if (c < KCHUNKS - 1) {
            storeA(s ^ 1);
            CP_WAIT0();
            __syncthreads();
        }
    }

#pragma unroll
    for (int mf = 0; mf < 2; mf++) {
        int r0 = bm + wm * 32 + mf * 16 + (lane >> 2);
#pragma unroll
        for (int nf = 0; nf < 6; nf++) {
            int col = bn + wn * 48 + nf * 8 + (lane & 3) * 2;
            float2 v0 = make_float2(acc[mf][nf][0] + g_bias[col],
                                    acc[mf][nf][1] + g_bias[col + 1]);
            float2 v1 = make_float2(acc[mf][nf][2] + g_bias[col],
                                    acc[mf][nf][3] + g_bias[col + 1]);
            *reinterpret_cast<float2*>(g_Y + (size_t)r0 * NPAD + col) = v0;
            *reinterpret_cast<float2*>(g_Y + (size_t)(r0 + 8) * NPAD + col) = v1;
        }
    }
}

// ----------------------------- epilogue ------------------------------------
__global__ __launch_bounds__(256) void epilogue_kernel(float* __restrict__ out) {
    const int warp = threadIdx.x >> 5;
    const int lane = threadIdx.x & 31;
    const int row  = blockIdx.x * 8 + warp;

    __shared__ float sY[8][352];
    __shared__ float sP[8][288];

    {
        const float4* yr4 = reinterpret_cast<const float4*>(g_Y + (size_t)row * NPAD);
        float4* sy4 = reinterpret_cast<float4*>(sY[warp]);
#pragma unroll
        for (int j = lane; j < 87; j += 32) sy4[j] = yr4[j];
    }
    __syncwarp();
    const float* s = sY[warp];

    float y0v = (lane < NCLS) ? s[lane] : -INFINITY;
    float m = y0v;
#pragma unroll
    for (int o = 16; o; o >>= 1) m = fmaxf(m, __shfl_xor_sync(0xFFFFFFFFu, m, o));
    float e = (lane < NCLS) ? expf(y0v - m) : 0.f;
    float ssum = e;
#pragma unroll
    for (int o = 16; o; o >>= 1) ssum += __shfl_xor_sync(0xFFFFFFFFu, ssum, o);
    float Pc = e / ssum;

    float best = -1.f;
    int bestk = 0;
    if (lane < NCLS) {
        const float* yc = s + 12 + lane * NCLU;
        float mc = -INFINITY;
#pragma unroll
        for (int k = 0; k < NCLU; k++) mc = fmaxf(mc, yc[k]);
        float sc = 0.f;
#pragma unroll
        for (int k = 0; k < NCLU; k++) sc += expf(yc[k] - mc);
        float inv = Pc / sc;
#pragma unroll
        for (int k = 0; k < NCLU; k++) {
            float p = expf(yc[k] - mc) * inv;
            sP[warp][k * NCLS + lane] = p;
            if (p > best) { best = p; bestk = k; }
        }
    }
    __syncwarp();

    // coalesced Plc writes: 72 float4 per row
    {
        const float4* sp4 = reinterpret_cast<const float4*>(sP[warp]);
        float4* po4 = reinterpret_cast<float4*>(out + PLC_OFF + (size_t)row * (NCLU * NCLS));
#pragma unroll
        for (int j = lane; j < 72; j += 32) po4[j] = sp4[j];
    }

    // argmax with first-flat-index tie-break
    float bv = best;
    int bi = bestk * NCLS + lane;
#pragma unroll
    for (int o = 16; o; o >>= 1) {
        float ov = __shfl_xor_sync(0xFFFFFFFFu, bv, o);
        int   oi = __shfl_xor_sync(0xFFFFFFFFu, bi, o);
        if (ov > bv || (ov == bv && oi < bi)) { bv = ov; bi = oi; }
    }
    const int ic = bi % NCLS;

    // candidate-class mask: classes whose per-class best Plc is within thresh of max
    unsigned cmask = __ballot_sync(0xFFFFFFFFu,
                                   (lane < NCLS) && (best >= bv - FLAG_THRESH * bv)) & 0xFFFu;
    if (lane == 0 && (cmask & (cmask - 1))) {   // >1 candidate class
        int p = atomicAdd(&g_flagcnt, 1);
        g_flagrows[p] = row | ((int)cmask << 14);
    }

    if (lane < NCLS) out[Y0_OFF + (size_t)row * NCLS + lane] = s[lane];
    if (lane < NCLU) out[Y1_OFF + (size_t)row * NCLU + lane] = s[12 + ic * NCLU + lane];
    if (lane < NDIM) out[Y2_OFF + (size_t)row * NDIM + lane] = s[300 + ic * NDIM + lane];
}

// ----------------------------- fp32 exact fixup (candidate classes only) ---
// 1024 threads = 32 warps; one warp per needed column (12 y0 + 24*ncand bins).
__global__ __launch_bounds__(1024) void fixup_kernel(const float* __restrict__ x,
                                                     float* __restrict__ out) {
    __shared__ float sx[N0];
    __shared__ float sy[NCOL];
    __shared__ int   wl[12 + NCLS * NCLU];
    __shared__ int   s_nwork;
    const int tid  = threadIdx.x;
    const int lane = tid & 31;
    const int wid  = tid >> 5;
    const int cnt  = g_flagcnt;

    for (int f = blockIdx.x; f < cnt; f += gridDim.x) {
        const int packed = g_flagrows[f];
        const int row   = packed & 0x3FFF;
        const int cmask = (packed >> 14) & 0xFFF;

        // x row -> smem (512 threads x float4)
        if (tid < 512) {
            *reinterpret_cast<float4*>(&sx[tid * 4]) =
                *reinterpret_cast<const float4*>(x + (size_t)row * N0 + tid * 4);
        }
        // build worklist
        if (tid < 12) wl[tid] = tid;
        if (tid < 12 && (cmask >> tid) & 1) {
            int pos = __popc(cmask & ((1 << tid) - 1));
            for (int k = 0; k < NCLU; k++)
                wl[12 + pos * NCLU + k] = 12 + tid * NCLU + k;
        }
        if (tid == 0) s_nwork = 12 + NCLU * __popc(cmask);
        __syncthreads();
        const int nwork = s_nwork;

        // one warp per column: coalesced float4 dot over g_Wc[col][k]
        for (int w = wid; w < nwork; w += 32) {
            int col = wl[w];
            const float4* wp = reinterpret_cast<const float4*>(&g_Wc[col * N0]);
            const float4* xp = reinterpret_cast<const float4*>(sx);
            float acc = 0.f;
#pragma unroll 8
            for (int i = lane; i < N0 / 4; i += 32) {
                float4 a = xp[i], b = wp[i];
                acc += a.x * b.x + a.y * b.y + a.z * b.z + a.w * b.w;
            }
#pragma unroll
            for (int o = 16; o; o >>= 1) acc += __shfl_xor_sync(0xFFFFFFFFu, acc, o);
            if (lane == 0) sy[col] = acc + g_bias[col];
        }
        __syncthreads();

        // decide winner among candidates with exact values, copy outputs from g_Y
        if (tid == 0) {
            float mm = -INFINITY;
            for (int c = 0; c < NCLS; c++) mm = fmaxf(mm, sy[c]);
            float ss = 0.f;
            for (int c = 0; c < NCLS; c++) ss += expf(sy[c] - mm);

            float bp = -1.f; int bi = 0x7FFFFFFF;
            for (int c = 0; c < NCLS; c++) {
                if (!((cmask >> c) & 1)) continue;
                float Pc = expf(sy[c] - mm) / ss;
                const float* yc = sy + 12 + c * NCLU;
                float mc = -INFINITY;
                for (int k = 0; k < NCLU; k++) mc = fmaxf(mc, yc[k]);
                float sc = 0.f;
                for (int k = 0; k < NCLU; k++) sc += expf(yc[k] - mc);
                float inv = Pc / sc;
                for (int k = 0; k < NCLU; k++) {
                    float p = expf(yc[k] - mc) * inv;
                    int flat = k * NCLS + c;
                    if (p > bp || (p == bp && flat < bi)) { bp = p; bi = flat; }
                }
            }
            int ic = bi % NCLS;
            const float* yr = g_Y + (size_t)row * NPAD;   // values match epilogue's source
            for (int k = 0; k < NCLU; k++)
                out[Y1_OFF + (size_t)row * NCLU + k] = yr[12 + ic * NCLU + k];
            for (int n = 0; n < NDIM; n++)
                out[Y2_OFF + (size_t)row * NDIM + n] = yr[300 + ic * NDIM + n];
        }
        __syncthreads();
    }
}

// ============================================================================
extern "C" void kernel_launch(void* const* d_in, const int* in_sizes, int n_in,
                              void* d_out, int out_size) {
    const float* x    = (const float*)d_in[0];
    const float* Wfc  = (const float*)d_in[1];
    const float* bfc  = (const float*)d_in[2];
    const float* Wbin = (const float*)d_in[3];
    const float* bbin = (const float*)d_in[4];
    const float* Wres = (const float*)d_in[5];
    const float* bres = (const float*)d_in[6];
    float* out = (float*)d_out;

    static bool attr_set = false;
    if (!attr_set) {
        cudaFuncSetAttribute(gemm_kernel, cudaFuncAttributeMaxDynamicSharedMemorySize, SMEM_TOTAL);
        attr_set = true;
    }

    pack_kernel<<<(PACK_TASKS + 255) / 256, 256>>>(Wfc, bfc, Wbin, bbin, Wres, bres);

    gemm_kernel<<<dim3(NPAD / BN, B_ROWS / BM), THREADS, SMEM_TOTAL>>>(x);

    epilogue_kernel<<<B_ROWS / 8, 256>>>(out);

    fixup_kernel<<<1024, 1024>>>(x, out);
}